// round 14
// baseline (speedup 1.0000x reference)
#include <cuda_runtime.h>
#include <cuda_fp16.h>
#include <cstdint>

#define NBLK 128
#define NTHR 256
typedef unsigned u32;
typedef unsigned long long u64;

// -------- device scratch --------
__device__ float d_XP[(size_t)64 * 512 * 3072];   // x-projections (+bias) [b*512+s][3072]
__device__ float d_hF[2][1024 * 64];              // h fp32 [col][b], double buffered
__device__ float d_z[1024 * 64];                  // z fp32 [col][b]
// k-blocked fp16 state (XOR-swizzled within rows), contiguous per k-group for bulk copy
__device__ __align__(16) unsigned short d_hA[4][64][256];   // [kg][b][k'&255]
__device__ __align__(16) unsigned short d_rhB[8][64][128];  // [kgB][b][k'&127]
__device__ float d_pA[(size_t)8 * 2048 * 64];     // phase-A partials [p][col][b]
__device__ float d_pB[(size_t)16 * 1024 * 64];    // phase-B partials [p][col][b]
// tree barrier: 16 group counters (128B apart) -> root -> generation
__device__ unsigned d_grp[16 * 32];
__device__ unsigned d_root;
__device__ unsigned d_gen;

// smem offsets (u16 units)
#define WA 0            // weights A: [64 cols][256 k] fp16, swizzled
#define WB 16384        // weights B: [64 cols][128 k]
#define STA 24576       // state buffer: [64 b][256] (A) or [64 b][128] (B)
#define MBARO_BYTES 81920
#define SMEM_BYTES 81936
#define HA_BYTES 32768
#define RB_BYTES 16384

// -------- helpers --------
__device__ __forceinline__ u64 dup2(float x){u64 r;asm("mov.b64 %0,{%1,%1};":"=l"(r):"f"(x));return r;}
__device__ __forceinline__ void fma2(u64&a,u64 x,u64 y){asm("fma.rn.f32x2 %0,%1,%2,%0;":"+l"(a):"l"(x),"l"(y));}
__device__ __forceinline__ float2 unp2(u64 v){float2 f;asm("mov.b64 {%0,%1},%2;":"=f"(f.x),"=f"(f.y):"l"(v));return f;}
__device__ __forceinline__ void lds128(u64&a,u64&b,unsigned ad){asm volatile("ld.shared.v2.u64 {%0,%1},[%2];":"=l"(a),"=l"(b):"r"(ad));}
__device__ __forceinline__ float sigmoidf(float x){return 1.f/(1.f+__expf(-x));}

// fp16 MMA, fp32 accumulate
__device__ __forceinline__ void mma_f16(float* c,const u32* a,const u32* b){
    asm volatile("mma.sync.aligned.m16n8k16.row.col.f32.f16.f16.f32 "
        "{%0,%1,%2,%3},{%4,%5,%6,%7},{%8,%9},{%0,%1,%2,%3};"
        : "+f"(c[0]),"+f"(c[1]),"+f"(c[2]),"+f"(c[3])
        : "r"(a[0]),"r"(a[1]),"r"(a[2]),"r"(a[3]),"r"(b[0]),"r"(b[1]));
}
__device__ __forceinline__ unsigned short h16(float x){
    return __half_as_ushort(__float2half_rn(x));
}
__device__ __forceinline__ u32 packu(unsigned short a,unsigned short b){
    return (u32)a|((u32)b<<16);
}
// bank-conflict-free word swizzle: word index ^= (row&7)*4
__device__ __forceinline__ int swz(int row,int w){return w^((row&7)<<2);}

// two-level tree grid barrier: 16 groups x 8 blocks -> root -> generation word.
// Monotone generation; replay-safe. Arrival atomics spread over 17 addresses.
__device__ __forceinline__ void gridbar(int grp){
    __syncthreads();
    if(threadIdx.x==0){
        asm volatile("fence.proxy.async;":::"memory");
        unsigned g;
        asm volatile("ld.acquire.gpu.u32 %0,[%1];":"=r"(g):"l"(&d_gen));
        unsigned a;
        asm volatile("atom.add.acq_rel.gpu.u32 %0,[%1],%2;"
                     :"=r"(a):"l"(&d_grp[grp*32]),"r"(1u):"memory");
        if((a&7u)==7u){
            unsigned b;
            asm volatile("atom.add.acq_rel.gpu.u32 %0,[%1],%2;"
                         :"=r"(b):"l"(&d_root),"r"(1u):"memory");
            if((b&15u)==15u){
                unsigned c;
                asm volatile("atom.add.release.gpu.u32 %0,[%1],%2;"
                             :"=r"(c):"l"(&d_gen),"r"(1u):"memory");
            }
        }
        unsigned cur;
        do{asm volatile("ld.acquire.gpu.u32 %0,[%1];":"=r"(cur):"l"(&d_gen));}while(cur==g);
    }
    __syncthreads();
}

__device__ __forceinline__ void mbar_init(u32 mb,u32 c){
    asm volatile("mbarrier.init.shared.b64 [%0],%1;"::"r"(mb),"r"(c):"memory");
}
__device__ __forceinline__ void mbar_expect(u32 mb,u32 bytes){
    asm volatile("mbarrier.arrive.expect_tx.shared.b64 _,[%0],%1;"::"r"(mb),"r"(bytes):"memory");
}
__device__ __forceinline__ void bulk_copy(u32 dst,const void* src,u32 bytes,u32 mb){
    asm volatile("cp.async.bulk.shared::cta.global.mbarrier::complete_tx::bytes [%0],[%1],%2,[%3];"
        ::"r"(dst),"l"(src),"r"(bytes),"r"(mb):"memory");
}
__device__ __forceinline__ void mbar_wait(u32 mb,u32 par){
    u32 done;
    do{asm volatile("{\n\t.reg .pred p;\n\t"
        "mbarrier.try_wait.parity.acquire.cta.shared::cta.b64 p,[%1],%2,0x989680;\n\t"
        "selp.b32 %0,1,0,p;\n\t}":"=r"(done):"r"(mb),"r"(par):"memory");}while(!done);
}

// -------- xproj (fp32, proven) --------
__global__ void __launch_bounds__(256) xproj_kernel(
    const float* __restrict__ x,
    const float* __restrict__ Wxz,const float* __restrict__ Wxr,const float* __restrict__ Wxh,
    const float* __restrict__ bz,const float* __restrict__ br,const float* __restrict__ bh){
    __shared__ float As[64*68],Bs[64*68];
    const int tid=threadIdx.x,ct=blockIdx.x,rt=blockIdx.y,wsel=ct>>4;
    const float* W=(wsel==0)?Wxz:((wsel==1)?Wxr:Wxh);
    const float* bias=(wsel==0)?bz:((wsel==1)?br:bh);
    const int colbase=(ct&15)*64,row0=rt*64,r4=(tid>>4)*4,c4=(tid&15)*4;
    u64 acc[4][2]={};
    for(int k0=0;k0<256;k0+=64){
        __syncthreads();
#pragma unroll
        for(int i=0;i<4;i++){int q=tid+i*256,rr=q>>4,kq=q&15;
            *(float4*)&As[rr*68+kq*4]=*(const float4*)&x[(size_t)(row0+rr)*256+k0+kq*4];}
#pragma unroll
        for(int i=0;i<4;i++){int q=tid+i*256,kk=q>>4,cq=q&15;
            *(float4*)&Bs[kk*68+cq*4]=*(const float4*)&W[(size_t)(k0+kk)*1024+colbase+cq*4];}
        __syncthreads();
        unsigned bs=(unsigned)__cvta_generic_to_shared(&Bs[c4]);
#pragma unroll 8
        for(int kk=0;kk<64;kk++){
            u64 bL,bH;lds128(bL,bH,bs+kk*68*4);
#pragma unroll
            for(int i=0;i<4;i++){u64 ad=dup2(As[(r4+i)*68+kk]);fma2(acc[i][0],ad,bL);fma2(acc[i][1],ad,bH);}
        }
    }
    float4 bb=*(const float4*)&bias[colbase+c4];
#pragma unroll
    for(int i=0;i<4;i++){
        float2 lo=unp2(acc[i][0]),hi=unp2(acc[i][1]);
        *(float4*)&d_XP[(size_t)(row0+r4+i)*3072+ct*64+c4]=make_float4(lo.x+bb.x,lo.y+bb.y,hi.x+bb.z,hi.y+bb.w);
    }
}

// -------- persistent GRU: fp16 HMMA single-pass, K-split blocks, tree barrier --------
__global__ void __launch_bounds__(NTHR,1) gru_kernel(
    const float* __restrict__ Whz,const float* __restrict__ Whr,const float* __restrict__ Whh){
    extern __shared__ unsigned short sm[];
    const int tid=threadIdx.x,bid=blockIdx.x,wid=tid>>5,lane=tid&31;
    const int cg=bid&31, kg=bid>>5;    // phase A: 32 col-groups(64) x 4 k-groups(256)
    const int cgB=bid&15,kgB=bid>>4;   // phase B: 16 col-groups(64) x 8 k-groups(128)
    const int grp=bid>>3;              // barrier group (16 groups of 8)
    u32 smb; asm("{ .reg .u64 t; cvta.to.shared.u64 t,%1; cvt.u32.u64 %0,t; }":"=r"(smb):"l"((void*)sm));
    const u32 mbar=smb+MBARO_BYTES;
    const u32 sta=smb+STA*2;

    // ---- load resident weight slices (fp16, swizzled [col][k]) ----
    {
        const int colg0=cg*64;
        const float* Wp=(colg0<1024)?(Whz+colg0):(Whr+colg0-1024);
#pragma unroll 4
        for(int i=0;i<64;i++){
            int idx=tid+i*NTHR,col=idx&63,k=idx>>6;
            float w=__ldg(&Wp[(size_t)(kg*256+k)*1024+col]);
            sm[WA+col*256+((swz(col,k>>1)<<1)|(k&1))]=h16(w);
        }
#pragma unroll 4
        for(int i=0;i<32;i++){
            int idx=tid+i*NTHR,col=idx&63,k=idx>>6;
            float w=__ldg(&Whh[(size_t)(kgB*128+k)*1024+cgB*64+col]);
            sm[WB+col*128+((swz(col,k>>1)<<1)|(k&1))]=h16(w);
        }
    }
    // ---- zero h state (fp32 + fp16 blocked) ----
    {
        int gid=bid*NTHR+tid;
        ((float2*)d_hF[0])[gid]=make_float2(0.f,0.f);
        ((u32*)d_hA)[gid]=0u;   // 128*256 = 32768 u32 = whole d_hA
    }
    if(tid==0)mbar_init(mbar,1);
    __syncthreads();
    gridbar(grp);

    const int mw=wid&1,nw=(wid>>1)&1,kw=wid>>2;
    const int g=lane>>2,tk=(lane&3)*2;
    const int ecpA=tid>>5, ebA=(tid*2)&63;
    const int cA0=bid*16+ecpA*2;
    const int ecB=bid*8+wid, eb=lane*2;
    u32 par=0;

    for(int s=0;s<512;s++){
        const int cur=s&1,nxt=cur^1;
        // ---- stage h slice via one bulk copy ----
        if(tid==0){
            mbar_expect(mbar,HA_BYTES);
            bulk_copy(sta,&d_hA[kg][0][0],HA_BYTES,mbar);
        }
        // prefetch epilogue-A operands
        float2 xpa=*(const float2*)&d_XP[((size_t)ebA*512+s)*3072+cA0];
        float2 xpb=*(const float2*)&d_XP[((size_t)(ebA+1)*512+s)*3072+cA0];
        float2 hA0=make_float2(0.f,0.f),hA1=hA0;
        if(bid>=64){
            hA0=__ldcg((const float2*)&d_hF[cur][(cA0-1024)*64+ebA]);
            hA1=__ldcg((const float2*)&d_hF[cur][(cA0-1023)*64+ebA]);
        }
        mbar_wait(mbar,par); par^=1;
        // ---- phase A MMA: warp m32n32, k-slice kw*128 ----
        float c[2][4][4];
#pragma unroll
        for(int mt=0;mt<2;mt++)
#pragma unroll
        for(int nt=0;nt<4;nt++)
#pragma unroll
        for(int q=0;q<4;q++)c[mt][nt][q]=0.f;
#pragma unroll 1
        for(int i=0;i<8;i++){
            int kk=kw*128+i*16+tk;
            int w0=kk>>1,w1=w0+4;
            u32 a[2][4],bfr[4][2];
#pragma unroll
            for(int mt=0;mt<2;mt++){
                int r=mw*32+mt*16+g;
                a[mt][0]=*(const u32*)&sm[WA+r*256+(swz(r,w0)<<1)];
                a[mt][1]=*(const u32*)&sm[WA+(r+8)*256+(swz(r+8,w0)<<1)];
                a[mt][2]=*(const u32*)&sm[WA+r*256+(swz(r,w1)<<1)];
                a[mt][3]=*(const u32*)&sm[WA+(r+8)*256+(swz(r+8,w1)<<1)];
            }
#pragma unroll
            for(int nt=0;nt<4;nt++){
                int b=nw*32+nt*8+g;
                bfr[nt][0]=*(const u32*)&sm[STA+b*256+(swz(b,w0)<<1)];
                bfr[nt][1]=*(const u32*)&sm[STA+b*256+(swz(b,w1)<<1)];
            }
#pragma unroll
            for(int mt=0;mt<2;mt++)
#pragma unroll
            for(int nt=0;nt<4;nt++)
                mma_f16(c[mt][nt],a[mt],bfr[nt]);
        }
        {
            int p=kg*2+kw;
#pragma unroll
            for(int mt=0;mt<2;mt++){
                int col=cg*64+mw*32+mt*16+g;
#pragma unroll
                for(int nt=0;nt<4;nt++){
                    int b=nw*32+nt*8+tk;
                    *(float2*)&d_pA[((size_t)p*2048+col)*64+b]=make_float2(c[mt][nt][0],c[mt][nt][1]);
                    *(float2*)&d_pA[((size_t)p*2048+col+8)*64+b]=make_float2(c[mt][nt][2],c[mt][nt][3]);
                }
            }
        }
        gridbar(grp);
        // ---- epilogue A: sum 8 partials -> sigmoid -> z or rh ----
        {
            float s0=0.f,s1=0.f,s2=0.f,s3=0.f;
#pragma unroll
            for(int p=0;p<8;p++){
                float2 v0=__ldcg((const float2*)&d_pA[((size_t)p*2048+cA0)*64+ebA]);
                float2 v1=__ldcg((const float2*)&d_pA[((size_t)p*2048+cA0+1)*64+ebA]);
                s0+=v0.x;s1+=v0.y;s2+=v1.x;s3+=v1.y;
            }
            float v00=sigmoidf(s0+xpa.x),v01=sigmoidf(s1+xpb.x);
            float v10=sigmoidf(s2+xpa.y),v11=sigmoidf(s3+xpb.y);
            if(bid<64){
                *(float2*)&d_z[cA0*64+ebA]      =make_float2(v00,v01);
                *(float2*)&d_z[(cA0+1)*64+ebA]  =make_float2(v10,v11);
            }else{
                int cp0=cA0-1024;
                int kgr=cp0>>7,w=(cp0&127)>>1;   // cp0 even
                float r00=v00*hA0.x,r01=v01*hA0.y;   // col cp0,  b ebA / ebA+1
                float r10=v10*hA1.x,r11=v11*hA1.y;   // col cp0+1
                *(u32*)&d_rhB[kgr][ebA][swz(ebA,w)<<1]    =packu(h16(r00),h16(r10));
                *(u32*)&d_rhB[kgr][ebA+1][swz(ebA+1,w)<<1]=packu(h16(r01),h16(r11));
            }
        }
        gridbar(grp);
        // ---- stage rh slice via one bulk copy ----
        if(tid==0){
            mbar_expect(mbar,RB_BYTES);
            bulk_copy(sta,&d_rhB[kgB][0][0],RB_BYTES,mbar);
        }
        // prefetch epilogue-B operands
        float xq0=__ldg(&d_XP[((size_t)eb*512+s)*3072+2048+ecB]);
        float xq1=__ldg(&d_XP[((size_t)(eb+1)*512+s)*3072+2048+ecB]);
        float2 zv=__ldcg((const float2*)&d_z[ecB*64+eb]);
        float2 hv=__ldcg((const float2*)&d_hF[cur][ecB*64+eb]);
        mbar_wait(mbar,par); par^=1;
        // ---- phase B MMA: warp m32n32, k-slice kw*64 ----
        float cb[2][4][4];
#pragma unroll
        for(int mt=0;mt<2;mt++)
#pragma unroll
        for(int nt=0;nt<4;nt++)
#pragma unroll
        for(int q=0;q<4;q++)cb[mt][nt][q]=0.f;
#pragma unroll 1
        for(int i=0;i<4;i++){
            int kk=kw*64+i*16+tk;
            int w0=kk>>1,w1=w0+4;
            u32 a[2][4],bfr[4][2];
#pragma unroll
            for(int mt=0;mt<2;mt++){
                int r=mw*32+mt*16+g;
                a[mt][0]=*(const u32*)&sm[WB+r*128+(swz(r,w0)<<1)];
                a[mt][1]=*(const u32*)&sm[WB+(r+8)*128+(swz(r+8,w0)<<1)];
                a[mt][2]=*(const u32*)&sm[WB+r*128+(swz(r,w1)<<1)];
                a[mt][3]=*(const u32*)&sm[WB+(r+8)*128+(swz(r+8,w1)<<1)];
            }
#pragma unroll
            for(int nt=0;nt<4;nt++){
                int b=nw*32+nt*8+g;
                bfr[nt][0]=*(const u32*)&sm[STA+b*128+(swz(b,w0)<<1)];
                bfr[nt][1]=*(const u32*)&sm[STA+b*128+(swz(b,w1)<<1)];
            }
#pragma unroll
            for(int mt=0;mt<2;mt++)
#pragma unroll
            for(int nt=0;nt<4;nt++)
                mma_f16(cb[mt][nt],a[mt],bfr[nt]);
        }
        {
            int p=kgB*2+kw;
#pragma unroll
            for(int mt=0;mt<2;mt++){
                int col=cgB*64+mw*32+mt*16+g;
#pragma unroll
                for(int nt=0;nt<4;nt++){
                    int b=nw*32+nt*8+tk;
                    *(float2*)&d_pB[((size_t)p*1024+col)*64+b]=make_float2(cb[mt][nt][0],cb[mt][nt][1]);
                    *(float2*)&d_pB[((size_t)p*1024+col+8)*64+b]=make_float2(cb[mt][nt][2],cb[mt][nt][3]);
                }
            }
        }
        gridbar(grp);
        // ---- epilogue B: sum 16 partials -> tanh -> h update ----
        {
            float n0=0.f,n1=0.f;
#pragma unroll
            for(int p=0;p<16;p++){
                float2 v=__ldcg((const float2*)&d_pB[((size_t)p*1024+ecB)*64+eb]);
                n0+=v.x;n1+=v.y;
            }
            n0=tanhf(n0+xq0); n1=tanhf(n1+xq1);
            float h0=(1.f-zv.x)*hv.x+zv.x*n0;
            float h1=(1.f-zv.y)*hv.y+zv.y*n1;
            *(float2*)&d_hF[nxt][ecB*64+eb]=make_float2(h0,h1);
            int kgh=ecB>>8,k1=ecB&255;
            d_hA[kgh][eb][(swz(eb,k1>>1)<<1)|(k1&1)]  =h16(h0);
            d_hA[kgh][eb+1][(swz(eb+1,k1>>1)<<1)|(k1&1)]=h16(h1);
        }
        gridbar(grp);
    }
}

// -------- head: out[b][o] = sum_k hF[0][k][b]*Wf[k][o] + bf[o] --------
__global__ void head_kernel(const float* __restrict__ Wf,const float* __restrict__ bf,float* __restrict__ out){
    const int b=blockIdx.x,o=threadIdx.x;
    const float* h=d_hF[0];   // after 512 steps final h is in buffer 0
    float acc=bf[o];
#pragma unroll 8
    for(int k=0;k<1024;k++)acc+=h[k*64+b]*Wf[(size_t)k*256+o];
    out[b*256+o]=acc;
}

extern "C" void kernel_launch(void* const* d_in,const int* in_sizes,int n_in,
                              void* d_out,int out_size){
    const float* x  =(const float*)d_in[0];
    const float* Wxz=(const float*)d_in[1];
    const float* Whz=(const float*)d_in[2];
    const float* Wxr=(const float*)d_in[3];
    const float* Whr=(const float*)d_in[4];
    const float* Wxh=(const float*)d_in[5];
    const float* Whh=(const float*)d_in[6];
    const float* bz =(const float*)d_in[7];
    const float* br =(const float*)d_in[8];
    const float* bh =(const float*)d_in[9];
    const float* Wf =(const float*)d_in[10];
    const float* bf =(const float*)d_in[11];
    float* out=(float*)d_out;

    dim3 gx(48,512);
    xproj_kernel<<<gx,256>>>(x,Wxz,Wxr,Wxh,bz,br,bh);
    cudaFuncSetAttribute(gru_kernel,cudaFuncAttributeMaxDynamicSharedMemorySize,SMEM_BYTES);
    gru_kernel<<<NBLK,NTHR,SMEM_BYTES>>>(Whz,Whr,Whh);
    head_kernel<<<64,256>>>(Wf,bf,out);
}

// round 15
// speedup vs baseline: 1.4571x; 1.4571x over previous
#include <cuda_runtime.h>
#include <cuda_fp16.h>
#include <cstdint>

#define NBLK 128
#define NTHR 256
typedef unsigned u32;
typedef unsigned long long u64;

// -------- device scratch --------
__device__ float d_XP[(size_t)64 * 512 * 3072];   // x-projections (+bias) [b*512+s][3072]
__device__ float d_hF[2][1024 * 64];              // h fp32 [col][b], double buffered
__device__ float d_z[2][1024 * 64];               // z fp32 [col][b], parity buffered
// k-blocked fp16 state (XOR-swizzled within rows), parity buffered
__device__ __align__(16) unsigned short d_hA[2][4][64][256];
__device__ __align__(16) unsigned short d_rhB[2][8][64][128];
__device__ float d_pA[2][(size_t)8 * 2048 * 64];  // phase-A partials [par][p][col][b]
__device__ float d_pB[2][(size_t)16 * 1024 * 64]; // phase-B partials [par][p][col][b]
__device__ unsigned d_count;                      // init barrier only (monotone)
// p2p counters: groups of 32 words (128B apart). Layout (in 32-word units):
//  [0,32)=pA cg ; [32,40)=rh slice ; [40,56)=pB cgB ; [56,60)=h slice ; [60,76)=z group
__device__ unsigned d_cnt[76 * 32];

// smem offsets (u16 units)
#define WA 0            // weights A: [64 cols][256 k] fp16, swizzled
#define WB 16384        // weights B: [64 cols][128 k]
#define STA 24576       // state buffer: [64 b][256] (A) or [64 b][128] (B)
#define MBARO_BYTES 81920
#define SMEM_BYTES 81936
#define HA_BYTES 32768
#define RB_BYTES 16384

// -------- helpers --------
__device__ __forceinline__ u64 dup2(float x){u64 r;asm("mov.b64 %0,{%1,%1};":"=l"(r):"f"(x));return r;}
__device__ __forceinline__ void fma2(u64&a,u64 x,u64 y){asm("fma.rn.f32x2 %0,%1,%2,%0;":"+l"(a):"l"(x),"l"(y));}
__device__ __forceinline__ float2 unp2(u64 v){float2 f;asm("mov.b64 {%0,%1},%2;":"=f"(f.x),"=f"(f.y):"l"(v));return f;}
__device__ __forceinline__ void lds128(u64&a,u64&b,unsigned ad){asm volatile("ld.shared.v2.u64 {%0,%1},[%2];":"=l"(a),"=l"(b):"r"(ad));}
__device__ __forceinline__ float sigmoidf(float x){return 1.f/(1.f+__expf(-x));}

__device__ __forceinline__ void mma_f16(float* c,const u32* a,const u32* b){
    asm volatile("mma.sync.aligned.m16n8k16.row.col.f32.f16.f16.f32 "
        "{%0,%1,%2,%3},{%4,%5,%6,%7},{%8,%9},{%0,%1,%2,%3};"
        : "+f"(c[0]),"+f"(c[1]),"+f"(c[2]),"+f"(c[3])
        : "r"(a[0]),"r"(a[1]),"r"(a[2]),"r"(a[3]),"r"(b[0]),"r"(b[1]));
}
__device__ __forceinline__ unsigned short h16(float x){
    return __half_as_ushort(__float2half_rn(x));
}
__device__ __forceinline__ u32 packu(unsigned short a,unsigned short b){
    return (u32)a|((u32)b<<16);
}
__device__ __forceinline__ int swz(int row,int w){return w^((row&7)<<2);}

// p2p sync primitives
__device__ __forceinline__ void sig(unsigned* p){
    unsigned o;asm volatile("atom.add.release.gpu.u32 %0,[%1],%2;":"=r"(o):"l"(p),"r"(1u):"memory");
}
__device__ __forceinline__ void waitge(const unsigned* p,unsigned tgt){
    unsigned c;do{asm volatile("ld.acquire.gpu.u32 %0,[%1];":"=r"(c):"l"(p));}while((int)(c-tgt)<0);
}
__device__ __forceinline__ void fpa(){asm volatile("fence.proxy.async;":::"memory");}

// init-only grid barrier (monotone, replay-safe)
__device__ __forceinline__ void gridbar(){
    __syncthreads();
    if(threadIdx.x==0){
        fpa();
        unsigned a;
        asm volatile("atom.add.release.gpu.u32 %0,[%1],%2;"
                     :"=r"(a):"l"(&d_count),"r"(1u):"memory");
        unsigned tg=a-(a&(NBLK-1))+NBLK,cur;
        do{asm volatile("ld.acquire.gpu.u32 %0,[%1];":"=r"(cur):"l"(&d_count));}while((int)(cur-tg)<0);
    }
    __syncthreads();
}

__device__ __forceinline__ void mbar_init(u32 mb,u32 c){
    asm volatile("mbarrier.init.shared.b64 [%0],%1;"::"r"(mb),"r"(c):"memory");
}
__device__ __forceinline__ void mbar_expect(u32 mb,u32 bytes){
    asm volatile("mbarrier.arrive.expect_tx.shared.b64 _,[%0],%1;"::"r"(mb),"r"(bytes):"memory");
}
__device__ __forceinline__ void bulk_copy(u32 dst,const void* src,u32 bytes,u32 mb){
    asm volatile("cp.async.bulk.shared::cta.global.mbarrier::complete_tx::bytes [%0],[%1],%2,[%3];"
        ::"r"(dst),"l"(src),"r"(bytes),"r"(mb):"memory");
}
__device__ __forceinline__ void mbar_wait(u32 mb,u32 par){
    u32 done;
    do{asm volatile("{\n\t.reg .pred p;\n\t"
        "mbarrier.try_wait.parity.acquire.cta.shared::cta.b64 p,[%1],%2,0x989680;\n\t"
        "selp.b32 %0,1,0,p;\n\t}":"=r"(done):"r"(mb),"r"(par):"memory");}while(!done);
}

// -------- xproj (fp32, proven) --------
__global__ void __launch_bounds__(256) xproj_kernel(
    const float* __restrict__ x,
    const float* __restrict__ Wxz,const float* __restrict__ Wxr,const float* __restrict__ Wxh,
    const float* __restrict__ bz,const float* __restrict__ br,const float* __restrict__ bh){
    __shared__ float As[64*68],Bs[64*68];
    const int tid=threadIdx.x,ct=blockIdx.x,rt=blockIdx.y,wsel=ct>>4;
    const float* W=(wsel==0)?Wxz:((wsel==1)?Wxr:Wxh);
    const float* bias=(wsel==0)?bz:((wsel==1)?br:bh);
    const int colbase=(ct&15)*64,row0=rt*64,r4=(tid>>4)*4,c4=(tid&15)*4;
    u64 acc[4][2]={};
    for(int k0=0;k0<256;k0+=64){
        __syncthreads();
#pragma unroll
        for(int i=0;i<4;i++){int q=tid+i*256,rr=q>>4,kq=q&15;
            *(float4*)&As[rr*68+kq*4]=*(const float4*)&x[(size_t)(row0+rr)*256+k0+kq*4];}
#pragma unroll
        for(int i=0;i<4;i++){int q=tid+i*256,kk=q>>4,cq=q&15;
            *(float4*)&Bs[kk*68+cq*4]=*(const float4*)&W[(size_t)(k0+kk)*1024+colbase+cq*4];}
        __syncthreads();
        unsigned bs=(unsigned)__cvta_generic_to_shared(&Bs[c4]);
#pragma unroll 8
        for(int kk=0;kk<64;kk++){
            u64 bL,bH;lds128(bL,bH,bs+kk*68*4);
#pragma unroll
            for(int i=0;i<4;i++){u64 ad=dup2(As[(r4+i)*68+kk]);fma2(acc[i][0],ad,bL);fma2(acc[i][1],ad,bH);}
        }
    }
    float4 bb=*(const float4*)&bias[colbase+c4];
#pragma unroll
    for(int i=0;i<4;i++){
        float2 lo=unp2(acc[i][0]),hi=unp2(acc[i][1]);
        *(float4*)&d_XP[(size_t)(row0+r4+i)*3072+ct*64+c4]=make_float4(lo.x+bb.x,lo.y+bb.y,hi.x+bb.z,hi.y+bb.w);
    }
}

// -------- persistent GRU: fp16 HMMA, K-split blocks, p2p producer/consumer sync --------
__global__ void __launch_bounds__(NTHR,1) gru_kernel(
    const float* __restrict__ Whz,const float* __restrict__ Whr,const float* __restrict__ Whh){
    extern __shared__ unsigned short sm[];
    const int tid=threadIdx.x,bid=blockIdx.x,wid=tid>>5,lane=tid&31;
    const int cg=bid&31, kg=bid>>5;    // phase A: 32 col-groups(64) x 4 k-groups(256)
    const int cgB=bid&15,kgB=bid>>4;   // phase B: 16 col-groups(64) x 8 k-groups(128)
    u32 smb; asm("{ .reg .u64 t; cvta.to.shared.u64 t,%1; cvt.u32.u64 %0,t; }":"=r"(smb):"l"((void*)sm));
    const u32 mbar=smb+MBARO_BYTES;
    const u32 sta=smb+STA*2;

    // counter addresses
    unsigned* cA_own =&d_cnt[(bid&31)*32];
    unsigned* cA_rd  =&d_cnt[(bid>>2)*32];             // epA partial group
    unsigned* cA_z   =&d_cnt[(bid>>3)*32];             // epB z-partial group
    unsigned* cRH_own=&d_cnt[(32+((bid-64)>>3))*32];   // valid only bid>=64
    unsigned* cRH_rd =&d_cnt[(32+kgB)*32];
    unsigned* cB_own =&d_cnt[(40+(bid&15))*32];
    unsigned* cB_rd  =&d_cnt[(40+(bid>>3))*32];
    unsigned* cH_own =&d_cnt[(56+(bid>>5))*32];
    unsigned* cH_s1  =&d_cnt[(56+kg)*32];              // staging slice (== own)
    unsigned* cH_pf  =&d_cnt[(56+((bid-64)>>4))*32];   // epA hF prefetch slice (bid>=64)
    unsigned* cZ_own =&d_cnt[(60+(bid>>2))*32];        // valid only bid<64
    unsigned* cZ_rd  =&d_cnt[(60+(bid>>3))*32];

    // ---- load resident weight slices (fp16, swizzled [col][k]) ----
    {
        const int colg0=cg*64;
        const float* Wp=(colg0<1024)?(Whz+colg0):(Whr+colg0-1024);
#pragma unroll 4
        for(int i=0;i<64;i++){
            int idx=tid+i*NTHR,col=idx&63,k=idx>>6;
            float w=__ldg(&Wp[(size_t)(kg*256+k)*1024+col]);
            sm[WA+col*256+((swz(col,k>>1)<<1)|(k&1))]=h16(w);
        }
#pragma unroll 4
        for(int i=0;i<32;i++){
            int idx=tid+i*NTHR,col=idx&63,k=idx>>6;
            float w=__ldg(&Whh[(size_t)(kgB*128+k)*1024+cgB*64+col]);
            sm[WB+col*128+((swz(col,k>>1)<<1)|(k&1))]=h16(w);
        }
    }
    // ---- zero h state + counters ----
    {
        int gid=bid*NTHR+tid;
        ((float2*)d_hF[0])[gid]=make_float2(0.f,0.f);
        ((u32*)d_hA)[gid]=0u;   // zeros d_hA[0] exactly (32768 u32)
        if(bid==0)for(int i=tid;i<76*32;i+=NTHR)d_cnt[i]=0u;
    }
    if(tid==0)mbar_init(mbar,1);
    __syncthreads();
    gridbar();

    const int mw=wid&1,nw=(wid>>1)&1,kw=wid>>2;
    const int g=lane>>2,tk=(lane&3)*2;
    const int ecpA=tid>>5, ebA=(tid*2)&63;
    const int cA0=bid*16+ecpA*2;
    const int ecB=bid*8+wid, eb=lane*2;
    u32 par=0;

    for(u32 s=0;s<512;s++){
        const int cur=s&1,nxt=cur^1;
        // ---- phase 1: wait h slices (prev step producers), stage, MMA A ----
        if(tid==0){
            unsigned tg=32u*s;
            waitge(cH_s1,tg);
            if(bid>=64)waitge(cH_pf,tg);
            waitge(&d_cnt[(56+(bid>>5))*32],tg);   // epB hv slice
        }
        __syncthreads();
        if(tid==0){
            mbar_expect(mbar,HA_BYTES);
            bulk_copy(sta,&d_hA[cur][kg][0][0],HA_BYTES,mbar);
        }
        float2 xpa=*(const float2*)&d_XP[((size_t)ebA*512+s)*3072+cA0];
        float2 xpb=*(const float2*)&d_XP[((size_t)(ebA+1)*512+s)*3072+cA0];
        float2 hA0=make_float2(0.f,0.f),hA1=hA0;
        if(bid>=64){
            hA0=__ldcg((const float2*)&d_hF[cur][(cA0-1024)*64+ebA]);
            hA1=__ldcg((const float2*)&d_hF[cur][(cA0-1023)*64+ebA]);
        }
        mbar_wait(mbar,par); par^=1;
        float c[2][4][4];
#pragma unroll
        for(int mt=0;mt<2;mt++)
#pragma unroll
        for(int nt=0;nt<4;nt++)
#pragma unroll
        for(int q=0;q<4;q++)c[mt][nt][q]=0.f;
#pragma unroll 1
        for(int i=0;i<8;i++){
            int kk=kw*128+i*16+tk;
            int w0=kk>>1,w1=w0+4;
            u32 a[2][4],bfr[4][2];
#pragma unroll
            for(int mt=0;mt<2;mt++){
                int r=mw*32+mt*16+g;
                a[mt][0]=*(const u32*)&sm[WA+r*256+(swz(r,w0)<<1)];
                a[mt][1]=*(const u32*)&sm[WA+(r+8)*256+(swz(r+8,w0)<<1)];
                a[mt][2]=*(const u32*)&sm[WA+r*256+(swz(r,w1)<<1)];
                a[mt][3]=*(const u32*)&sm[WA+(r+8)*256+(swz(r+8,w1)<<1)];
            }
#pragma unroll
            for(int nt=0;nt<4;nt++){
                int b=nw*32+nt*8+g;
                bfr[nt][0]=*(const u32*)&sm[STA+b*256+(swz(b,w0)<<1)];
                bfr[nt][1]=*(const u32*)&sm[STA+b*256+(swz(b,w1)<<1)];
            }
#pragma unroll
            for(int mt=0;mt<2;mt++)
#pragma unroll
            for(int nt=0;nt<4;nt++)
                mma_f16(c[mt][nt],a[mt],bfr[nt]);
        }
        {
            int p=kg*2+kw;
            float* pa=d_pA[cur];
#pragma unroll
            for(int mt=0;mt<2;mt++){
                int col=cg*64+mw*32+mt*16+g;
#pragma unroll
                for(int nt=0;nt<4;nt++){
                    int b=nw*32+nt*8+tk;
                    *(float2*)&pa[((size_t)p*2048+col)*64+b]=make_float2(c[mt][nt][0],c[mt][nt][1]);
                    *(float2*)&pa[((size_t)p*2048+col+8)*64+b]=make_float2(c[mt][nt][2],c[mt][nt][3]);
                }
            }
        }
        __syncthreads();
        if(tid==0){ sig(cA_own); waitge(cA_rd,4u*(s+1)); }
        __syncthreads();
        // ---- epilogue A: sum 4-producer partials -> sigmoid -> z or rh ----
        {
            const float* pa=d_pA[cur];
            float s0=0.f,s1=0.f,s2=0.f,s3=0.f;
#pragma unroll
            for(int p=0;p<8;p++){
                float2 v0=__ldcg((const float2*)&pa[((size_t)p*2048+cA0)*64+ebA]);
                float2 v1=__ldcg((const float2*)&pa[((size_t)p*2048+cA0+1)*64+ebA]);
                s0+=v0.x;s1+=v0.y;s2+=v1.x;s3+=v1.y;
            }
            float v00=sigmoidf(s0+xpa.x),v01=sigmoidf(s1+xpb.x);
            float v10=sigmoidf(s2+xpa.y),v11=sigmoidf(s3+xpb.y);
            if(bid<64){
                *(float2*)&d_z[cur][cA0*64+ebA]      =make_float2(v00,v01);
                *(float2*)&d_z[cur][(cA0+1)*64+ebA]  =make_float2(v10,v11);
            }else{
                int cp0=cA0-1024;
                int kgr=cp0>>7,w=(cp0&127)>>1;
                float r00=v00*hA0.x,r01=v01*hA0.y;
                float r10=v10*hA1.x,r11=v11*hA1.y;
                *(u32*)&d_rhB[cur][kgr][ebA][swz(ebA,w)<<1]    =packu(h16(r00),h16(r10));
                *(u32*)&d_rhB[cur][kgr][ebA+1][swz(ebA+1,w)<<1]=packu(h16(r01),h16(r11));
            }
        }
        __syncthreads();
        if(tid==0){
            fpa();
            if(bid<64)sig(cZ_own);else sig(cRH_own);
            waitge(cRH_rd,8u*(s+1));
            waitge(cZ_rd,4u*(s+1));
        }
        __syncthreads();
        // ---- phase 3: stage rh, MMA B ----
        if(tid==0){
            mbar_expect(mbar,RB_BYTES);
            bulk_copy(sta,&d_rhB[cur][kgB][0][0],RB_BYTES,mbar);
        }
        float xq0=__ldg(&d_XP[((size_t)eb*512+s)*3072+2048+ecB]);
        float xq1=__ldg(&d_XP[((size_t)(eb+1)*512+s)*3072+2048+ecB]);
        float2 zv=__ldcg((const float2*)&d_z[cur][ecB*64+eb]);
        float2 hv=__ldcg((const float2*)&d_hF[cur][ecB*64+eb]);
        mbar_wait(mbar,par); par^=1;
        float cb[2][4][4];
#pragma unroll
        for(int mt=0;mt<2;mt++)
#pragma unroll
        for(int nt=0;nt<4;nt++)
#pragma unroll
        for(int q=0;q<4;q++)cb[mt][nt][q]=0.f;
#pragma unroll 1
        for(int i=0;i<4;i++){
            int kk=kw*64+i*16+tk;
            int w0=kk>>1,w1=w0+4;
            u32 a[2][4],bfr[4][2];
#pragma unroll
            for(int mt=0;mt<2;mt++){
                int r=mw*32+mt*16+g;
                a[mt][0]=*(const u32*)&sm[WB+r*128+(swz(r,w0)<<1)];
                a[mt][1]=*(const u32*)&sm[WB+(r+8)*128+(swz(r+8,w0)<<1)];
                a[mt][2]=*(const u32*)&sm[WB+r*128+(swz(r,w1)<<1)];
                a[mt][3]=*(const u32*)&sm[WB+(r+8)*128+(swz(r+8,w1)<<1)];
            }
#pragma unroll
            for(int nt=0;nt<4;nt++){
                int b=nw*32+nt*8+g;
                bfr[nt][0]=*(const u32*)&sm[STA+b*128+(swz(b,w0)<<1)];
                bfr[nt][1]=*(const u32*)&sm[STA+b*128+(swz(b,w1)<<1)];
            }
#pragma unroll
            for(int mt=0;mt<2;mt++)
#pragma unroll
            for(int nt=0;nt<4;nt++)
                mma_f16(cb[mt][nt],a[mt],bfr[nt]);
        }
        {
            int p=kgB*2+kw;
            float* pb=d_pB[cur];
#pragma unroll
            for(int mt=0;mt<2;mt++){
                int col=cgB*64+mw*32+mt*16+g;
#pragma unroll
                for(int nt=0;nt<4;nt++){
                    int b=nw*32+nt*8+tk;
                    *(float2*)&pb[((size_t)p*1024+col)*64+b]=make_float2(cb[mt][nt][0],cb[mt][nt][1]);
                    *(float2*)&pb[((size_t)p*1024+col+8)*64+b]=make_float2(cb[mt][nt][2],cb[mt][nt][3]);
                }
            }
        }
        __syncthreads();
        if(tid==0){
            sig(cB_own);
            waitge(cB_rd,8u*(s+1));
            waitge(cA_z,4u*(s+1));
        }
        __syncthreads();
        // ---- epilogue B: z from pA, n from pB, h update ----
        {
            const float* pa=d_pA[cur];
            const float* pb=d_pB[cur];
            float z0=0.f,z1=0.f,n0=0.f,n1=0.f;
#pragma unroll
            for(int p=0;p<8;p++){
                float2 v=__ldcg((const float2*)&pa[((size_t)p*2048+ecB)*64+eb]);
                z0+=v.x;z1+=v.y;
            }
#pragma unroll
            for(int p=0;p<16;p++){
                float2 v=__ldcg((const float2*)&pb[((size_t)p*1024+ecB)*64+eb]);
                n0+=v.x;n1+=v.y;
            }
            // z = sigmoid(zsum + xpz); note: zsum partials already include K-split halves
            float xpz0=__ldg(&d_XP[((size_t)eb*512+s)*3072+ecB]);
            float xpz1=__ldg(&d_XP[((size_t)(eb+1)*512+s)*3072+ecB]);
            z0=sigmoidf(z0+xpz0); z1=sigmoidf(z1+xpz1);
            // but z was ALSO computed in epilogue A -> use that value for exactness
            z0=zv.x; z1=zv.y;
            n0=tanhf(n0+xq0); n1=tanhf(n1+xq1);
            float h0=(1.f-z0)*hv.x+z0*n0;
            float h1=(1.f-z1)*hv.y+z1*n1;
            *(float2*)&d_hF[nxt][ecB*64+eb]=make_float2(h0,h1);
            int kgh=ecB>>8,k1=ecB&255;
            d_hA[nxt][kgh][eb][(swz(eb,k1>>1)<<1)|(k1&1)]  =h16(h0);
            d_hA[nxt][kgh][eb+1][(swz(eb+1,k1>>1)<<1)|(k1&1)]=h16(h1);
        }
        __syncthreads();
        if(tid==0){ fpa(); sig(cH_own); }
    }
}

// -------- head: out[b][o] = sum_k hF[0][k][b]*Wf[k][o] + bf[o] --------
__global__ void head_kernel(const float* __restrict__ Wf,const float* __restrict__ bf,float* __restrict__ out){
    const int b=blockIdx.x,o=threadIdx.x;
    const float* h=d_hF[0];   // after 512 steps final h is in buffer 0
    float acc=bf[o];
#pragma unroll 8
    for(int k=0;k<1024;k++)acc+=h[k*64+b]*Wf[(size_t)k*256+o];
    out[b*256+o]=acc;
}

extern "C" void kernel_launch(void* const* d_in,const int* in_sizes,int n_in,
                              void* d_out,int out_size){
    const float* x  =(const float*)d_in[0];
    const float* Wxz=(const float*)d_in[1];
    const float* Whz=(const float*)d_in[2];
    const float* Wxr=(const float*)d_in[3];
    const float* Whr=(const float*)d_in[4];
    const float* Wxh=(const float*)d_in[5];
    const float* Whh=(const float*)d_in[6];
    const float* bz =(const float*)d_in[7];
    const float* br =(const float*)d_in[8];
    const float* bh =(const float*)d_in[9];
    const float* Wf =(const float*)d_in[10];
    const float* bf =(const float*)d_in[11];
    float* out=(float*)d_out;

    dim3 gx(48,512);
    xproj_kernel<<<gx,256>>>(x,Wxz,Wxr,Wxh,bz,br,bh);
    cudaFuncSetAttribute(gru_kernel,cudaFuncAttributeMaxDynamicSharedMemorySize,SMEM_BYTES);
    gru_kernel<<<NBLK,NTHR,SMEM_BYTES>>>(Whz,Whr,Whh);
    head_kernel<<<64,256>>>(Wf,bf,out);
}